// round 10
// baseline (speedup 1.0000x reference)
#include <cuda_runtime.h>
#include <math.h>

// ---------------- problem constants ----------------
#define DD     128
#define NCLS   32
#define GTPB   288
#define BATCH  16
#define MAXM   (1 << 19)
#define MAXCTA 512

// ---------------- device scratch ----------------
__device__ float  g_cov[NCLS + 1][DD][DD];
__device__ int    g_chunk_cnt[MAXCTA][NCLS];
__device__ int    g_counts[NCLS];
__device__ int    g_class_start[NCLS + 1];
__device__ int    g_order[MAXM];
__device__ double g_logdet[NCLS + 1];
__device__ int           g_bcnt[8];
__device__ volatile int  g_bflag[8];

// ---------------- reset barrier state (graph node 1) ----------------
__global__ void k_reset() {
    if (threadIdx.x < 8) { g_bcnt[threadIdx.x] = 0; g_bflag[threadIdx.x] = 0; }
}

// ---------------- software grid barrier (all CTAs resident) ----------------
__device__ __forceinline__ void gbar(int i) {
    __syncthreads();
    if (threadIdx.x == 0) {
        __threadfence();
        int t = atomicAdd(&g_bcnt[i], 1);
        if (t == (int)gridDim.x - 1) {
            g_bflag[i] = 1;
        } else {
            long long guard = 0;
            while (g_bflag[i] == 0 && guard < (1LL << 31)) guard++;
        }
        __threadfence();
    }
    __syncthreads();
}

// ---------------- gemm helpers (R9-proven) ----------------
typedef unsigned long long u64t;

__device__ __forceinline__ void accum_row2(const float* __restrict__ row,
                                           int ti, int tj, u64t acc[8][4]) {
    float4 a0 = *(const float4*)(row + (ti << 3));
    float4 a1 = *(const float4*)(row + (ti << 3) + 4);
    ulonglong2 bq0 = *(const ulonglong2*)(row + (tj << 3));
    ulonglong2 bq1 = *(const ulonglong2*)(row + (tj << 3) + 4);
    u64t bp[4] = {bq0.x, bq0.y, bq1.x, bq1.y};
    float av[8] = {a0.x, a0.y, a0.z, a0.w, a1.x, a1.y, a1.z, a1.w};
#pragma unroll
    for (int a = 0; a < 8; a++) {
        u64t ad;
        asm("mov.b64 %0, {%1, %1};" : "=l"(ad) : "f"(av[a]));
#pragma unroll
        for (int b = 0; b < 4; b++)
            asm("fma.rn.f32x2 %0, %1, %2, %0;" : "+l"(acc[a][b]) : "l"(ad), "l"(bp[b]));
    }
}

__device__ __forceinline__ void flush_acc2(int cls, int ti, int tj, u64t acc[8][4]) {
#pragma unroll
    for (int a = 0; a < 8; a++)
#pragma unroll
        for (int b = 0; b < 4; b++) {
            float lo, hi;
            asm("mov.b64 {%0, %1}, %2;" : "=f"(lo), "=f"(hi) : "l"(acc[a][b]));
            int r = ti * 8 + a, c = tj * 8 + 2 * b;
            atomicAdd(&g_cov[cls][r][c],      lo);
            atomicAdd(&g_cov[NCLS][r][c],     lo);
            atomicAdd(&g_cov[cls][r][c + 1],  hi);
            atomicAdd(&g_cov[NCLS][r][c + 1], hi);
            acc[a][b] = 0ull;
        }
}

// ---------------- THE fused kernel ----------------
__global__ void __launch_bounds__(GTPB, 2)
k_fused(const float* __restrict__ Z, const int* __restrict__ label,
        float* __restrict__ out, int M, int CH, int nchunk) {
    extern __shared__ char dyn[];              // 66048 B union
    __shared__ int    s_cnt[NCLS];
    __shared__ float  s_col[DD];
    __shared__ double s_pivot;
    __shared__ double s_diag[DD];
    __shared__ double s_red[DD];

    int tid = threadIdx.x;
    int b   = blockIdx.x;
    int wid = tid >> 5, lane = tid & 31;

    // ======== Phase A: per-chunk histogram + zero g_cov ========
    if (tid < NCLS) s_cnt[tid] = 0;
    __syncthreads();
    {
        int base = b * CH;
        int end  = min(base + CH, M);
        for (int r = base + tid; r < end; r += GTPB)
            atomicAdd(&s_cnt[label[r]], 1);
    }
    __syncthreads();
    if (tid < NCLS && b < nchunk) g_chunk_cnt[b][tid] = s_cnt[tid];
    {
        float* cf = &g_cov[0][0][0];
        const int TOT = (NCLS + 1) * DD * DD;
        for (int i = b * GTPB + tid; i < TOT; i += gridDim.x * GTPB)
            cf[i] = 0.0f;
    }
    gbar(0);

    // ======== Phase B: offsets (CTA 0, serial-per-class, proven) ========
    if (b == 0) {
        int j = tid;
        if (j < NCLS) {
            int tot = 0;
            for (int c = 0; c < nchunk; c++) tot += g_chunk_cnt[c][j];
            g_counts[j] = tot;
        }
        __syncthreads();
        if (j == 0) {
            int s = 0;
            for (int jj = 0; jj < NCLS; jj++) { g_class_start[jj] = s; s += g_counts[jj]; }
            g_class_start[NCLS] = s;
        }
        __syncthreads();
        if (j < NCLS) {
            int s = g_class_start[j];
            for (int c = 0; c < nchunk; c++) {
                int v = g_chunk_cnt[c][j];
                g_chunk_cnt[c][j] = s;
                s += v;
            }
        }
    }
    gbar(1);

    // ======== Phase C: stable class-sorted order (proven) ========
    if (b < nchunk) {
        int* lbl = (int*)dyn;
        int base = b * CH;
        int n = min(CH, M - base);
        for (int i = tid; i < n; i += GTPB) lbl[i] = label[base + i];
        __syncthreads();
        if (tid < NCLS) {
            int pos = g_chunk_cnt[b][tid];
            for (int r = 0; r < n; r++)
                if (lbl[r] == tid) {
                    if (pos >= 0 && pos < MAXM) g_order[pos] = base + r;
                    pos++;
                }
        }
    }
    gbar(2);

    // ======== Phase D: segmented A^T A (R9-proven body) ========
    {
        float (*s_rows)[BATCH][DD] = (float (*)[BATCH][DD])dyn;   // 16 KB
        int p0 = b * CH;
        if (p0 < M) {
            int pend = min(p0 + CH, M);

            int grp = (tid >= 144) ? 1 : 0;
            int id  = tid - grp * 144;
            int ti = -1, tj = -1;
            if (id < 136) {
                int i = 0, rem = id;
                while (rem >= 16 - i) { rem -= 16 - i; i++; }
                ti = i; tj = i + rem;
            }

            u64t acc[8][4];
#pragma unroll
            for (int a = 0; a < 8; a++)
#pragma unroll
                for (int c = 0; c < 4; c++) acc[a][c] = 0ull;

            int cur = 0;
            while (cur < NCLS - 1 && g_class_start[cur + 1] <= p0) cur++;
            int nextb = g_class_start[cur + 1];

            int srow = 2 * wid + (lane >> 4);
            int scol = lane & 15;

            if (wid < 8) {
                int pos = p0 + srow;
                if (pos < pend) {
                    int row = g_order[pos];
                    const float4* src = (const float4*)(Z + (size_t)row * DD);
                    float4* dst = (float4*)s_rows[0][srow];
                    dst[scol]      = src[scol];
                    dst[scol + 16] = src[scol + 16];
                }
            }
            __syncthreads();

            int ib = 0;
            for (int p = p0; p < pend; p += BATCH, ib ^= 1) {
                int nb = min(BATCH, pend - p);
                if (wid < 8 && p + BATCH < pend) {
                    int pos = p + BATCH + srow;
                    if (pos < pend) {
                        int row = g_order[pos];
                        const float4* src = (const float4*)(Z + (size_t)row * DD);
                        float4* dst = (float4*)s_rows[ib ^ 1][srow];
                        dst[scol]      = src[scol];
                        dst[scol + 16] = src[scol + 16];
                    }
                }

                if (nb == BATCH && p + BATCH <= nextb) {
                    if (ti >= 0) {
#pragma unroll
                        for (int k = 0; k < BATCH; k += 2)
                            accum_row2(s_rows[ib][k + grp], ti, tj, acc);
                    }
                } else {
                    for (int k = 0; k < nb; k++) {
                        if (p + k >= nextb && cur < NCLS - 1) {
                            if (ti >= 0) flush_acc2(cur, ti, tj, acc);
                            cur++;
                            while (cur < NCLS - 1 && g_class_start[cur + 1] <= p + k) cur++;
                            nextb = g_class_start[cur + 1];
                        }
                        if (ti >= 0 && (k & 1) == grp)
                            accum_row2(s_rows[ib][k], ti, tj, acc);
                    }
                }
                __syncthreads();
            }
            if (ti >= 0) flush_acc2(cur, ti, tj, acc);
        }
    }
    gbar(3);

    // ======== Phase E: fp32 Cholesky + fp64 diag (CTAs 0..32, proven) ========
    if (b <= NCLS) {
        float* sA = (float*)dyn;               // 66048 B
        const int LDA = DD + 1;
        int j = b;
        const float (*C)[DD] = g_cov[j];
        double mydiag = 0.0;
        if (tid < DD) {
            for (int c = 0; c < DD; c++) {
                int lo = min(tid, c), hi = max(tid, c);
                sA[tid * LDA + c] = C[lo][hi];
            }
            mydiag = (double)C[tid][tid];
        }
        __syncthreads();

        for (int k = 0; k < DD; k++) {
            if (tid == k) { s_pivot = mydiag; s_diag[k] = mydiag; }
            __syncthreads();
            float inv = rsqrtf((float)s_pivot);
            float lrk = 0.0f;
            if (tid > k && tid < DD) {
                lrk = sA[tid * LDA + k] * inv;
                s_col[tid] = lrk;
                mydiag -= (double)lrk * (double)lrk;
            }
            __syncthreads();
            if (tid > k && tid < DD) {
                float* rowp = &sA[tid * LDA];
                int c = k + 1;
                for (; c + 3 < tid; c += 4) {
                    rowp[c + 0] -= lrk * s_col[c + 0];
                    rowp[c + 1] -= lrk * s_col[c + 1];
                    rowp[c + 2] -= lrk * s_col[c + 2];
                    rowp[c + 3] -= lrk * s_col[c + 3];
                }
                for (; c < tid; c++) rowp[c] -= lrk * s_col[c];
            }
            __syncthreads();
        }
        if (tid < DD) s_red[tid] = log(s_diag[tid]);
        __syncthreads();
        for (int s = DD / 2; s > 0; s >>= 1) {
            if (tid < s) s_red[tid] += s_red[tid + s];
            __syncthreads();
        }
        if (tid == 0) g_logdet[j] = s_red[0];
    }
    gbar(4);

    // ======== Phase F: finalize (CTA 0, one warp, proven) ========
    if (b == 0 && tid < 32) {
        double m = (double)M;
        double term = 0.0;
        if (tid < NCLS) {
            int mj = g_counts[tid];
            if (mj > 0) {
                double cj = (double)DD / ((double)mj * 0.01);
                term = ((double)DD * log(cj) + g_logdet[tid]) * (double)mj / (2.0 * m);
            }
        }
#pragma unroll
        for (int d = 16; d > 0; d >>= 1)
            term += __shfl_down_sync(0xFFFFFFFFu, term, d);
        if (tid == 0) {
            double c = (double)DD / (m * 0.01);
            double expd = ((double)DD * log(c) + g_logdet[NCLS]) * 0.5;
            out[0] = (float)(term - expd);
        }
    }
}

// ---------------- launch ----------------
extern "C" void kernel_launch(void* const* d_in, const int* in_sizes, int n_in,
                              void* d_out, int out_size) {
    const float* Z     = (const float*)d_in[0];
    const int*   label = (const int*)d_in[1];
    int M = in_sizes[1];

    int nsm = 0;
    cudaDeviceGetAttribute(&nsm, cudaDevAttrMultiProcessorCount, 0);
    if (nsm <= 0) nsm = 148;
    int ncta = 2 * nsm;
    if (ncta > MAXCTA) ncta = MAXCTA;
    // chunk size: ceil(M/ncta) rounded up to BATCH multiple
    int ch = (M + ncta - 1) / ncta;
    ch = (ch + BATCH - 1) & ~(BATCH - 1);
    int nchunk = (M + ch - 1) / ch;            // <= ncta by construction

    const int DYN = DD * (DD + 1) * (int)sizeof(float);   // 66048
    cudaFuncSetAttribute(k_fused, cudaFuncAttributeMaxDynamicSharedMemorySize, DYN);

    k_reset<<<1, 32>>>();
    k_fused<<<ncta, GTPB, DYN>>>(Z, label, (float*)d_out, M, ch, nchunk);
}

// round 11
// speedup vs baseline: 1.0540x; 1.0540x over previous
#include <cuda_runtime.h>
#include <math.h>

// ---------------- problem constants ----------------
#define DD     128          // feature dim
#define NCLS   32           // number of classes
#define OCHUNK 1024         // rows per hist/order chunk
#define GCHUNK 896          // rows per gemm CTA (multiple of BATCH)
#define MAXCHUNK 1024
#define GTPB   288          // gemm threads per block
#define BATCH  16           // rows staged per smem batch
#define MAXM   (1 << 19)

// ---------------- device scratch ----------------
__device__ float  g_cov[NCLS + 1][DD][DD];      // [32] = global (dual-atomic flush)
__device__ int    g_chunk_cnt[MAXCHUNK][NCLS];  // raw counts (never overwritten)
__device__ int    g_counts[NCLS];
__device__ int    g_class_start[NCLS + 1];
__device__ int    g_order[MAXM];
__device__ double g_logdet[NCLS + 1];
__device__ int    g_done;

// ---------------- K1: per-chunk histogram + zero cov + reset g_done ----------
__global__ void k_hist(const int* __restrict__ label, int M) {
    __shared__ int cnt[NCLS];
    int tid = threadIdx.x, b = blockIdx.x;
    if (b == 0 && tid == 0) g_done = 0;
    if (tid < NCLS) cnt[tid] = 0;
    __syncthreads();
    int base = b * OCHUNK;
    int end  = min(base + OCHUNK, M);
    for (int r = base + tid; r < end; r += blockDim.x)
        atomicAdd(&cnt[label[r]], 1);
    __syncthreads();
    if (tid < NCLS) g_chunk_cnt[b][tid] = cnt[tid];

    float* cf = &g_cov[0][0][0];
    const int TOT = (NCLS + 1) * DD * DD;
    for (int i = b * blockDim.x + tid; i < TOT; i += gridDim.x * blockDim.x)
        cf[i] = 0.0f;
}

// ------- K2: order with fused (redundant per-CTA) scan --------------------
// Each CTA recomputes, from the read-only g_chunk_cnt: per-class totals,
// class starts, and the prefix of its own chunk. Then does the proven stable
// write loop. CTA 0 additionally publishes g_counts / g_class_start.
__global__ void k_order2(const int* __restrict__ label, int M, int nchunk) {
    __shared__ int lbl[OCHUNK];
    __shared__ int s_tot[NCLS];
    __shared__ int s_pre[NCLS];
    __shared__ int s_cls[NCLS + 1];
    int tid = threadIdx.x, b = blockIdx.x;
    int base = b * OCHUNK;
    int n = min(OCHUNK, M - base);
    for (int i = tid; i < n; i += blockDim.x) lbl[i] = label[base + i];

    if (tid < NCLS) {
        int tot = 0, pre = 0;
        for (int c = 0; c < nchunk; c++) {
            int v = g_chunk_cnt[c][tid];     // coalesced: one 128B line per iter
            tot += v;
            if (c < b) pre += v;
        }
        s_tot[tid] = tot;
        s_pre[tid] = pre;
    }
    __syncthreads();
    if (tid == 0) {
        int s = 0;
        for (int j = 0; j < NCLS; j++) { s_cls[j] = s; s += s_tot[j]; }
        s_cls[NCLS] = s;
    }
    __syncthreads();

    if (tid < NCLS) {
        int pos = s_cls[tid] + s_pre[tid];
        for (int r = 0; r < n; r++)
            if (lbl[r] == tid) {
                if (pos >= 0 && pos < MAXM) g_order[pos] = base + r;
                pos++;
            }
    }
    if (b == 0 && tid <= NCLS) {
        if (tid < NCLS) g_counts[tid] = s_tot[tid];
        g_class_start[tid] = s_cls[tid];
    }
}

// ---------------- K3: segmented A^T A (R9-proven, dual-atomic flush) --------
typedef unsigned long long u64t;

__device__ __forceinline__ void accum_row2(const float* __restrict__ row,
                                           int ti, int tj, u64t acc[8][4]) {
    float4 a0 = *(const float4*)(row + (ti << 3));
    float4 a1 = *(const float4*)(row + (ti << 3) + 4);
    ulonglong2 bq0 = *(const ulonglong2*)(row + (tj << 3));
    ulonglong2 bq1 = *(const ulonglong2*)(row + (tj << 3) + 4);
    u64t bp[4] = {bq0.x, bq0.y, bq1.x, bq1.y};
    float av[8] = {a0.x, a0.y, a0.z, a0.w, a1.x, a1.y, a1.z, a1.w};
#pragma unroll
    for (int a = 0; a < 8; a++) {
        u64t ad;
        asm("mov.b64 %0, {%1, %1};" : "=l"(ad) : "f"(av[a]));
#pragma unroll
        for (int b = 0; b < 4; b++)
            asm("fma.rn.f32x2 %0, %1, %2, %0;" : "+l"(acc[a][b]) : "l"(ad), "l"(bp[b]));
    }
}

__device__ __forceinline__ void flush_acc2(int cls, int ti, int tj, u64t acc[8][4]) {
#pragma unroll
    for (int a = 0; a < 8; a++)
#pragma unroll
        for (int b = 0; b < 4; b++) {
            float lo, hi;
            asm("mov.b64 {%0, %1}, %2;" : "=f"(lo), "=f"(hi) : "l"(acc[a][b]));
            int r = ti * 8 + a, c = tj * 8 + 2 * b;
            atomicAdd(&g_cov[cls][r][c],      lo);
            atomicAdd(&g_cov[NCLS][r][c],     lo);
            atomicAdd(&g_cov[cls][r][c + 1],  hi);
            atomicAdd(&g_cov[NCLS][r][c + 1], hi);
            acc[a][b] = 0ull;
        }
}

__global__ void __launch_bounds__(GTPB, 2) k_gemm(const float* __restrict__ Z, int M) {
    __shared__ float s_rows[2][BATCH][DD];   // 16 KB, double buffered
    int tid = threadIdx.x;
    int wid = tid >> 5, lane = tid & 31;
    int p0 = blockIdx.x * GCHUNK;
    if (p0 >= M) return;
    int pend = min(p0 + GCHUNK, M);

    int grp = (tid >= 144) ? 1 : 0;
    int id  = tid - grp * 144;
    int ti = -1, tj = -1;
    if (id < 136) {
        int i = 0, rem = id;
        while (rem >= 16 - i) { rem -= 16 - i; i++; }
        ti = i; tj = i + rem;
    }

    u64t acc[8][4];
#pragma unroll
    for (int a = 0; a < 8; a++)
#pragma unroll
        for (int b = 0; b < 4; b++) acc[a][b] = 0ull;

    int cur = 0;
    while (cur < NCLS - 1 && g_class_start[cur + 1] <= p0) cur++;
    int nextb = g_class_start[cur + 1];

    int srow = 2 * wid + (lane >> 4);
    int scol = lane & 15;

    if (wid < 8) {
        int pos = p0 + srow;
        if (pos < pend) {
            int row = g_order[pos];
            const float4* src = (const float4*)(Z + (size_t)row * DD);
            float4* dst = (float4*)s_rows[0][srow];
            dst[scol]      = src[scol];
            dst[scol + 16] = src[scol + 16];
        }
    }
    __syncthreads();

    int ib = 0;
    for (int p = p0; p < pend; p += BATCH, ib ^= 1) {
        int nb = min(BATCH, pend - p);
        if (wid < 8 && p + BATCH < pend) {
            int pos = p + BATCH + srow;
            if (pos < pend) {
                int row = g_order[pos];
                const float4* src = (const float4*)(Z + (size_t)row * DD);
                float4* dst = (float4*)s_rows[ib ^ 1][srow];
                dst[scol]      = src[scol];
                dst[scol + 16] = src[scol + 16];
            }
        }

        if (nb == BATCH && p + BATCH <= nextb) {
            if (ti >= 0) {
#pragma unroll
                for (int k = 0; k < BATCH; k += 2)
                    accum_row2(s_rows[ib][k + grp], ti, tj, acc);
            }
        } else {
            for (int k = 0; k < nb; k++) {
                if (p + k >= nextb && cur < NCLS - 1) {
                    if (ti >= 0) flush_acc2(cur, ti, tj, acc);
                    cur++;
                    while (cur < NCLS - 1 && g_class_start[cur + 1] <= p + k) cur++;
                    nextb = g_class_start[cur + 1];
                }
                if (ti >= 0 && (k & 1) == grp)
                    accum_row2(s_rows[ib][k], ti, tj, acc);
            }
        }
        __syncthreads();
    }
    if (ti >= 0) flush_acc2(cur, ti, tj, acc);
}

// ------- K4: Cholesky (proven, log-hoisted) + last-block finalize -----------
__global__ void k_chol_fin(float* __restrict__ out, int M) {
    extern __shared__ float sA[];             // DD x (DD+1) floats
    __shared__ float  s_col[DD];
    __shared__ double s_pivot;
    __shared__ double s_diag[DD];
    __shared__ double s_red[DD];
    __shared__ int    s_last;
    const int LDA = DD + 1;
    int j = blockIdx.x;                        // 0..31 class, 32 global
    int tid = threadIdx.x;                     // 0..127

    bool has = (j == NCLS) || (g_counts[j] > 0);   // uniform per block

    if (has) {
        const float (*C)[DD] = g_cov[j];
        for (int c = 0; c < DD; c++) {
            int lo = min(tid, c), hi = max(tid, c);
            sA[tid * LDA + c] = C[lo][hi];
        }
        double mydiag = (double)C[tid][tid];
        __syncthreads();

        for (int k = 0; k < DD; k++) {
            if (tid == k) { s_pivot = mydiag; s_diag[k] = mydiag; }
            __syncthreads();
            float inv = rsqrtf((float)s_pivot);
            float lrk = 0.0f;
            if (tid > k) {
                lrk = sA[tid * LDA + k] * inv;
                s_col[tid] = lrk;
                mydiag -= (double)lrk * (double)lrk;
            }
            __syncthreads();
            if (tid > k) {
                float* rowp = &sA[tid * LDA];
                int c = k + 1;
                for (; c + 3 < tid; c += 4) {
                    rowp[c + 0] -= lrk * s_col[c + 0];
                    rowp[c + 1] -= lrk * s_col[c + 1];
                    rowp[c + 2] -= lrk * s_col[c + 2];
                    rowp[c + 3] -= lrk * s_col[c + 3];
                }
                for (; c < tid; c++) rowp[c] -= lrk * s_col[c];
            }
            __syncthreads();
        }
        s_red[tid] = log(s_diag[tid]);
        __syncthreads();
        for (int s = DD / 2; s > 0; s >>= 1) {
            if (tid < s) s_red[tid] += s_red[tid + s];
            __syncthreads();
        }
        if (tid == 0) g_logdet[j] = s_red[0];
    } else {
        if (tid == 0) g_logdet[j] = 0.0;
    }

    // ---- last block to finish runs the finalize ----
    __syncthreads();
    __threadfence();
    if (tid == 0) s_last = (atomicAdd(&g_done, 1) == NCLS) ? 1 : 0;
    __syncthreads();
    if (s_last && tid < 32) {
        double m = (double)M;
        double term = 0.0;
        if (tid < NCLS) {
            int mj = g_counts[tid];
            if (mj > 0) {
                double cj = (double)DD / ((double)mj * 0.01);
                double ld = __ldcg(&g_logdet[tid]);      // L2 read: fresh values
                term = ((double)DD * log(cj) + ld) * (double)mj / (2.0 * m);
            }
        }
#pragma unroll
        for (int d = 16; d > 0; d >>= 1)
            term += __shfl_down_sync(0xFFFFFFFFu, term, d);
        if (tid == 0) {
            double c = (double)DD / (m * 0.01);
            double expd = ((double)DD * log(c) + __ldcg(&g_logdet[NCLS])) * 0.5;
            out[0] = (float)(term - expd);
        }
    }
}

// ---------------- launch ----------------
extern "C" void kernel_launch(void* const* d_in, const int* in_sizes, int n_in,
                              void* d_out, int out_size) {
    const float* Z     = (const float*)d_in[0];
    const int*   label = (const int*)d_in[1];
    int M = in_sizes[1];
    int nchunk = (M + OCHUNK - 1) / OCHUNK;
    int ggrid  = (M + GCHUNK - 1) / GCHUNK;

    cudaFuncSetAttribute(k_chol_fin, cudaFuncAttributeMaxDynamicSharedMemorySize,
                         DD * (DD + 1) * (int)sizeof(float));

    k_hist<<<nchunk, 256>>>(label, M);
    k_order2<<<nchunk, 256>>>(label, M, nchunk);
    k_gemm<<<ggrid, GTPB>>>(Z, M);
    k_chol_fin<<<NCLS + 1, DD, DD * (DD + 1) * (int)sizeof(float)>>>((float*)d_out, M);
}

// round 12
// speedup vs baseline: 1.3967x; 1.3251x over previous
#include <cuda_runtime.h>
#include <math.h>

// ---------------- problem constants ----------------
#define DD     128          // feature dim
#define NCLS   32           // number of classes
#define OCHUNK 1024         // rows per hist/order chunk
#define GCHUNK 896          // rows per gemm CTA (multiple of BATCH)
#define MAXCHUNK 1024
#define GTPB   288          // gemm threads per block (9 warps)
#define BATCH  16           // rows staged per smem batch
#define MAXM   (1 << 19)
#define SCAN_GROUPS 16      // supports nchunk <= 512

// cholesky kernel config
#define CTPB   512
#define NPAIRS ((DD * (DD - 1)) / 2)   // 8128 strictly-lower elements
#define PPT    16                      // pairs per thread (512*16 = 8192 >= 8128)

// ---------------- device scratch ----------------
__device__ float  g_cov[NCLS + 1][DD][DD];      // [32] = global (k_sumglobal)
__device__ int    g_chunk_cnt[MAXCHUNK][NCLS];
__device__ int    g_counts[NCLS];
__device__ int    g_class_start[NCLS + 1];
__device__ int    g_order[MAXM];
__device__ double g_logdet[NCLS + 1];

// ---------------- K1: per-chunk histogram + zero cov (proven R9) -------------
__global__ void k_hist(const int* __restrict__ label, int M) {
    __shared__ int cnt[NCLS];
    int tid = threadIdx.x, b = blockIdx.x;
    if (tid < NCLS) cnt[tid] = 0;
    __syncthreads();
    int base = b * OCHUNK;
    int end  = min(base + OCHUNK, M);
    for (int r = base + tid; r < end; r += blockDim.x)
        atomicAdd(&cnt[label[r]], 1);
    __syncthreads();
    if (tid < NCLS) g_chunk_cnt[b][tid] = cnt[tid];

    float* cf = &g_cov[0][0][0];
    const int TOT = (NCLS + 1) * DD * DD;
    for (int i = b * blockDim.x + tid; i < TOT; i += gridDim.x * blockDim.x)
        cf[i] = 0.0f;
}

// ------- K2: parallel offsets (proven R9). Warp j = class j. ----------------
__global__ void k_scan(int nchunk) {
    __shared__ int s_tot[NCLS];
    __shared__ int s_start[NCLS + 1];
    int j = threadIdx.x >> 5;
    int l = threadIdx.x & 31;

    int c[SCAN_GROUPS], excl[SCAN_GROUPS];
    int run = 0;
#pragma unroll
    for (int i = 0; i < SCAN_GROUPS; i++) {
        int b = 32 * i + l;
        c[i] = (b < nchunk) ? g_chunk_cnt[b][j] : 0;
        int incl = c[i];
#pragma unroll
        for (int d = 1; d < 32; d <<= 1) {
            int v = __shfl_up_sync(0xFFFFFFFFu, incl, d);
            if (l >= d) incl += v;
        }
        excl[i] = run + (incl - c[i]);
        run += __shfl_sync(0xFFFFFFFFu, incl, 31);
    }
    if (l == 0) s_tot[j] = run;
    __syncthreads();
    if (threadIdx.x == 0) {
        int s = 0;
        for (int jj = 0; jj < NCLS; jj++) { s_start[jj] = s; s += s_tot[jj]; }
        s_start[NCLS] = s;
    }
    __syncthreads();
    if (l == 0) {
        g_counts[j] = s_tot[j];
        g_class_start[j] = s_start[j];
        if (j == 0) g_class_start[NCLS] = s_start[NCLS];
    }
    int base = s_start[j];
#pragma unroll
    for (int i = 0; i < SCAN_GROUPS; i++) {
        int b = 32 * i + l;
        if (b < nchunk) g_chunk_cnt[b][j] = base + excl[i];
    }
}

// ---------------- K3: stable class-sorted order (proven R9) -----------------
__global__ void k_order(const int* __restrict__ label, int M) {
    __shared__ int lbl[OCHUNK];
    int tid = threadIdx.x, b = blockIdx.x;
    int base = b * OCHUNK;
    int n = min(OCHUNK, M - base);
    for (int i = tid; i < n; i += blockDim.x) lbl[i] = label[base + i];
    __syncthreads();
    if (tid < NCLS) {
        int pos = g_chunk_cnt[b][tid];
        for (int r = 0; r < n; r++)
            if (lbl[r] == tid) {
                if (pos >= 0 && pos < MAXM) g_order[pos] = base + r;
                pos++;
            }
    }
}

// ---------------- K4: segmented A^T A (R9-proven, verbatim) -----------------
typedef unsigned long long u64t;

__device__ __forceinline__ void accum_row2(const float* __restrict__ row,
                                           int ti, int tj, u64t acc[8][4]) {
    float4 a0 = *(const float4*)(row + (ti << 3));
    float4 a1 = *(const float4*)(row + (ti << 3) + 4);
    ulonglong2 bq0 = *(const ulonglong2*)(row + (tj << 3));
    ulonglong2 bq1 = *(const ulonglong2*)(row + (tj << 3) + 4);
    u64t bp[4] = {bq0.x, bq0.y, bq1.x, bq1.y};
    float av[8] = {a0.x, a0.y, a0.z, a0.w, a1.x, a1.y, a1.z, a1.w};
#pragma unroll
    for (int a = 0; a < 8; a++) {
        u64t ad;
        asm("mov.b64 %0, {%1, %1};" : "=l"(ad) : "f"(av[a]));
#pragma unroll
        for (int b = 0; b < 4; b++)
            asm("fma.rn.f32x2 %0, %1, %2, %0;" : "+l"(acc[a][b]) : "l"(ad), "l"(bp[b]));
    }
}

__device__ __forceinline__ void flush_acc2(int cls, int ti, int tj, u64t acc[8][4]) {
#pragma unroll
    for (int a = 0; a < 8; a++)
#pragma unroll
        for (int b = 0; b < 4; b++) {
            float lo, hi;
            asm("mov.b64 {%0, %1}, %2;" : "=f"(lo), "=f"(hi) : "l"(acc[a][b]));
            int r = ti * 8 + a, c = tj * 8 + 2 * b;
            atomicAdd(&g_cov[cls][r][c],     lo);
            atomicAdd(&g_cov[cls][r][c + 1], hi);
            acc[a][b] = 0ull;
        }
}

__global__ void __launch_bounds__(GTPB, 2) k_gemm(const float* __restrict__ Z, int M) {
    __shared__ float s_rows[2][BATCH][DD];   // 16 KB, double buffered
    int tid = threadIdx.x;
    int wid = tid >> 5, lane = tid & 31;
    int p0 = blockIdx.x * GCHUNK;
    if (p0 >= M) return;
    int pend = min(p0 + GCHUNK, M);

    int grp = (tid >= 144) ? 1 : 0;
    int id  = tid - grp * 144;
    int ti = -1, tj = -1;
    if (id < 136) {
        int i = 0, rem = id;
        while (rem >= 16 - i) { rem -= 16 - i; i++; }
        ti = i; tj = i + rem;
    }

    u64t acc[8][4];
#pragma unroll
    for (int a = 0; a < 8; a++)
#pragma unroll
        for (int b = 0; b < 4; b++) acc[a][b] = 0ull;

    int cur = 0;
    while (cur < NCLS - 1 && g_class_start[cur + 1] <= p0) cur++;
    int nextb = g_class_start[cur + 1];

    int srow = 2 * wid + (lane >> 4);
    int scol = lane & 15;

    if (wid < 8) {
        int pos = p0 + srow;
        if (pos < pend) {
            int row = g_order[pos];
            const float4* src = (const float4*)(Z + (size_t)row * DD);
            float4* dst = (float4*)s_rows[0][srow];
            dst[scol]      = src[scol];
            dst[scol + 16] = src[scol + 16];
        }
    }
    __syncthreads();

    int ib = 0;
    for (int p = p0; p < pend; p += BATCH, ib ^= 1) {
        int nb = min(BATCH, pend - p);
        if (wid < 8 && p + BATCH < pend) {
            int pos = p + BATCH + srow;
            if (pos < pend) {
                int row = g_order[pos];
                const float4* src = (const float4*)(Z + (size_t)row * DD);
                float4* dst = (float4*)s_rows[ib ^ 1][srow];
                dst[scol]      = src[scol];
                dst[scol + 16] = src[scol + 16];
            }
        }

        if (nb == BATCH && p + BATCH <= nextb) {
            if (ti >= 0) {
#pragma unroll
                for (int k = 0; k < BATCH; k += 2)
                    accum_row2(s_rows[ib][k + grp], ti, tj, acc);
            }
        } else {
            for (int k = 0; k < nb; k++) {
                if (p + k >= nextb && cur < NCLS - 1) {
                    if (ti >= 0) flush_acc2(cur, ti, tj, acc);
                    cur++;
                    while (cur < NCLS - 1 && g_class_start[cur + 1] <= p + k) cur++;
                    nextb = g_class_start[cur + 1];
                }
                if (ti >= 0 && (k & 1) == grp)
                    accum_row2(s_rows[ib][k], ti, tj, acc);
            }
        }
        __syncthreads();
    }
    if (ti >= 0) flush_acc2(cur, ti, tj, acc);
}

// ---------------- K4b: global cov = sum of class covs (proven) --------------
__global__ void k_sumglobal(void) {
    int r = blockIdx.x, c = threadIdx.x;
    float s = 0.0f;
#pragma unroll
    for (int j = 0; j < NCLS; j++) s += g_cov[j][r][c];
    g_cov[NCLS][r][c] = s;
}

// ------- K5: NEW Cholesky — register-resident trailing matrix, 512 threads ---
// Element (r,c), c<r, lives in a register of its owner. Per step: row threads
// scale column k (phase 1, fp64-compensated diagonals, double-buffered pivot);
// all threads update their active pairs and publish column k+1 (phase 2).
// fp32 update order per element is identical to the proven thread-per-row code.
__global__ void __launch_bounds__(CTPB) k_cholesky(void) {
    __shared__ float  s_colraw[DD];      // unscaled current column
    __shared__ float  s_col[DD];         // scaled column  L[:,k]
    __shared__ float  s_piv[2];          // double-buffered pivot
    __shared__ double s_diag[DD];
    __shared__ double s_red[DD];
    int j = blockIdx.x;                   // 0..31 class, 32 global
    int tid = threadIdx.x;

    if (j < NCLS && g_counts[j] == 0) {
        if (tid == 0) g_logdet[j] = 0.0;
        return;
    }
    const float (*C)[DD] = g_cov[j];

    // decode + load owned pairs (strided: p = tid + 512*i -> coalesced loads)
    int   prc[PPT];
    float pv[PPT];
#pragma unroll
    for (int i = 0; i < PPT; i++) {
        int p = tid + CTPB * i;
        if (p < NPAIRS) {
            int r = (int)((1.0f + sqrtf(1.0f + 8.0f * (float)p)) * 0.5f);
            while (r * (r - 1) / 2 > p) r--;
            while ((r + 1) * r / 2 <= p) r++;
            int c = p - r * (r - 1) / 2;       // 0 <= c < r < 128
            prc[i] = (r << 16) | c;
            pv[i]  = C[c][r];                   // upper-stored symmetric
        } else {
            prc[i] = (127 << 16) | 0;          // inert dummy (c=0 never active)
            pv[i]  = 0.0f;
        }
    }

    double mydiag = 0.0;
    if (tid < DD) {
        s_colraw[tid] = C[0][tid];             // column 0
        mydiag = (double)C[tid][tid];
        if (tid == 0) { s_piv[0] = (float)mydiag; s_diag[0] = mydiag; }
    }
    __syncthreads();

    for (int k = 0; k < DD; k++) {
        // phase 1: scale column k; compensated diagonal; publish next pivot
        if (tid < DD && tid > k) {
            float inv = rsqrtf(s_piv[k & 1]);
            float lrk = s_colraw[tid] * inv;
            s_col[tid] = lrk;
            mydiag -= (double)lrk * (double)lrk;
            if (tid == k + 1) {
                s_piv[(k + 1) & 1] = (float)mydiag;
                s_diag[tid] = mydiag;
            }
        }
        __syncthreads();
        // phase 2: rank-1 update of owned pairs; publish column k+1
#pragma unroll
        for (int i = 0; i < PPT; i++) {
            int c = prc[i] & 0xFFFF;
            if (c > k) {
                int r = prc[i] >> 16;
                pv[i] -= s_col[r] * s_col[c];
                if (c == k + 1) s_colraw[r] = pv[i];
            }
        }
        __syncthreads();
    }

    if (tid < DD) s_red[tid] = log(s_diag[tid]);
    __syncthreads();
    for (int s = DD / 2; s > 0; s >>= 1) {
        if (tid < s) s_red[tid] += s_red[tid + s];
        __syncthreads();
    }
    if (tid == 0) g_logdet[j] = s_red[0];
}

// ---------------- K6: combine (one warp, proven) ----------------
__global__ void k_finalize(float* out, int M) {
    int lane = threadIdx.x;
    double m = (double)M;
    double term = 0.0;
    if (lane < NCLS) {
        int mj = g_counts[lane];
        if (mj > 0) {
            double cj = (double)DD / ((double)mj * 0.01);
            term = ((double)DD * log(cj) + g_logdet[lane]) * (double)mj / (2.0 * m);
        }
    }
#pragma unroll
    for (int d = 16; d > 0; d >>= 1)
        term += __shfl_down_sync(0xFFFFFFFFu, term, d);
    if (lane == 0) {
        double c = (double)DD / (m * 0.01);
        double expd = ((double)DD * log(c) + g_logdet[NCLS]) * 0.5;
        out[0] = (float)(term - expd);
    }
}

// ---------------- launch ----------------
extern "C" void kernel_launch(void* const* d_in, const int* in_sizes, int n_in,
                              void* d_out, int out_size) {
    const float* Z     = (const float*)d_in[0];
    const int*   label = (const int*)d_in[1];
    int M = in_sizes[1];
    int nchunk = (M + OCHUNK - 1) / OCHUNK;
    int ggrid  = (M + GCHUNK - 1) / GCHUNK;

    k_hist<<<nchunk, 256>>>(label, M);
    k_scan<<<1, 1024>>>(nchunk);
    k_order<<<nchunk, 256>>>(label, M);
    k_gemm<<<ggrid, GTPB>>>(Z, M);
    k_sumglobal<<<DD, DD>>>();
    k_cholesky<<<NCLS + 1, CTPB>>>();
    k_finalize<<<1, 32>>>((float*)d_out, M);
}